// round 1
// baseline (speedup 1.0000x reference)
#include <cuda_runtime.h>

// Problem constants
#define T_LEN   4096
#define D_DIM   512
#define N_DIM   16
#define TWO_N   32
#define DQ      128            // D/4 (float4 groups per row)
#define SEG     64             // number of segments
#define L_SEG   64             // steps per segment (SEG*L_SEG == T_LEN)
#define CG      2048           // chain groups = N*D/4
#define BIG_THREADS (SEG*CG)   // 131072

// Scratch (device globals: no allocation allowed)
__device__ float4 g_b  [SEG*CG];   // ha forcing per (seg, chain-group)
__device__ float4 g_f  [SEG*CG];   // hv forcing per (seg, chain-group)
__device__ float4 g_hab[SEG*CG];   // ha boundary at segment start
__device__ float4 g_hvb[SEG*CG];   // hv boundary at segment start

__device__ __forceinline__ float sqrt_approx(float v) {
    float r;
    asm("sqrt.approx.f32 %0, %1;" : "=f"(r) : "f"(v));
    return r;
}

// ---------------------------------------------------------------------------
// K1: zero-state ha replay per segment -> forcing term b
// ---------------------------------------------------------------------------
__global__ void k_b(const float4* __restrict__ x4, const float4* __restrict__ a4p) {
    int tid = blockIdx.x * blockDim.x + threadIdx.x;
    int s  = tid >> 11;          // segment
    int cg = tid & (CG - 1);     // chain group (n*128 + g)
    int g  = cg & (DQ - 1);

    float4 a = a4p[cg];
    float qx = 0.f, qy = 0.f, qz = 0.f, qw = 0.f;
    const float4* xp = x4 + (size_t)(s * L_SEG) * DQ + g;

    #pragma unroll 4
    for (int i = 0; i < L_SEG; i++) {
        float4 xv = xp[(size_t)i * DQ];
        qx = fmaf(a.x, xv.x - qx, qx);
        qy = fmaf(a.y, xv.y - qy, qy);
        qz = fmaf(a.z, xv.z - qz, qz);
        qw = fmaf(a.w, xv.w - qw, qw);
    }
    g_b[s * CG + cg] = make_float4(qx, qy, qz, qw);
}

// ---------------------------------------------------------------------------
// K2: sequential combine of ha boundaries (2048 threads)
// ---------------------------------------------------------------------------
__global__ void k_ha(const float4* __restrict__ ha0p, const float4* __restrict__ a4p) {
    int cg = blockIdx.x * blockDim.x + threadIdx.x;
    float4 a = a4p[cg];
    // p = (1-alpha)^64 via 6 squarings
    float px = 1.f - a.x, py = 1.f - a.y, pz = 1.f - a.z, pw = 1.f - a.w;
    #pragma unroll
    for (int k = 0; k < 6; k++) { px *= px; py *= py; pz *= pz; pw *= pw; }

    float4 ha = ha0p[cg];
    #pragma unroll 1
    for (int s = 0; s < SEG; s++) {
        g_hab[s * CG + cg] = ha;
        float4 b = g_b[s * CG + cg];
        ha.x = fmaf(px, ha.x, b.x);
        ha.y = fmaf(py, ha.y, b.y);
        ha.z = fmaf(pz, ha.z, b.z);
        ha.w = fmaf(pw, ha.w, b.w);
    }
}

// ---------------------------------------------------------------------------
// K3: replay ha from true boundary, write out_a, accumulate hv forcing f
// ---------------------------------------------------------------------------
__global__ void k_a(const float4* __restrict__ x4, const float4* __restrict__ a4p,
                    float4* __restrict__ out4) {
    int tid = blockIdx.x * blockDim.x + threadIdx.x;
    int s  = tid >> 11;
    int cg = tid & (CG - 1);
    int n  = cg >> 7;
    int g  = cg & (DQ - 1);

    float4 a = a4p[cg];
    float omx = 1.f - a.x, omy = 1.f - a.y, omz = 1.f - a.z, omw = 1.f - a.w;

    float4 ha = g_hab[s * CG + cg];
    float fx = 0.f, fy = 0.f, fz = 0.f, fw = 0.f;
    int t0 = s * L_SEG;

    #pragma unroll 4
    for (int i = 0; i < L_SEG; i++) {
        int t = t0 + i;
        float4 xv = x4[(size_t)t * DQ + g];
        float ux = xv.x - ha.x, uy = xv.y - ha.y, uz = xv.z - ha.z, uw = xv.w - ha.w;
        fx = omx * fmaf(a.x, ux * ux, fx);
        fy = omy * fmaf(a.y, uy * uy, fy);
        fz = omz * fmaf(a.z, uz * uz, fz);
        fw = omw * fmaf(a.w, uw * uw, fw);
        ha.x = fmaf(a.x, ux, ha.x);
        ha.y = fmaf(a.y, uy, ha.y);
        ha.z = fmaf(a.z, uz, ha.z);
        ha.w = fmaf(a.w, uw, ha.w);
        out4[((size_t)t * TWO_N + n) * DQ + g] = ha;
    }
    g_f[s * CG + cg] = make_float4(fx, fy, fz, fw);
}

// ---------------------------------------------------------------------------
// K4: sequential combine of hv boundaries (2048 threads)
// ---------------------------------------------------------------------------
__global__ void k_hv(const float4* __restrict__ hs0p, const float4* __restrict__ a4p) {
    int cg = blockIdx.x * blockDim.x + threadIdx.x;
    float4 a = a4p[cg];
    float px = 1.f - a.x, py = 1.f - a.y, pz = 1.f - a.z, pw = 1.f - a.w;
    #pragma unroll
    for (int k = 0; k < 6; k++) { px *= px; py *= py; pz *= pz; pw *= pw; }

    float4 hs = hs0p[cg];
    float hx = hs.x * hs.x, hy = hs.y * hs.y, hz = hs.z * hs.z, hw = hs.w * hs.w;
    #pragma unroll 1
    for (int s = 0; s < SEG; s++) {
        g_hvb[s * CG + cg] = make_float4(hx, hy, hz, hw);
        float4 f = g_f[s * CG + cg];
        hx = fmaf(px, hx, f.x);
        hy = fmaf(py, hy, f.y);
        hz = fmaf(pz, hz, f.z);
        hw = fmaf(pw, hw, f.w);
    }
}

// ---------------------------------------------------------------------------
// K5: full replay from true boundaries, write out_s (+ final states)
// ---------------------------------------------------------------------------
__global__ void k_s(const float4* __restrict__ x4, const float4* __restrict__ a4p,
                    float4* __restrict__ out4) {
    int tid = blockIdx.x * blockDim.x + threadIdx.x;
    int s  = tid >> 11;
    int cg = tid & (CG - 1);
    int n  = cg >> 7;
    int g  = cg & (DQ - 1);

    float4 a = a4p[cg];
    float omx = 1.f - a.x, omy = 1.f - a.y, omz = 1.f - a.z, omw = 1.f - a.w;

    float4 ha = g_hab[s * CG + cg];
    float4 hv = g_hvb[s * CG + cg];
    int t0 = s * L_SEG;

    #pragma unroll 4
    for (int i = 0; i < L_SEG; i++) {
        int t = t0 + i;
        float4 xv = x4[(size_t)t * DQ + g];
        float ux = xv.x - ha.x, uy = xv.y - ha.y, uz = xv.z - ha.z, uw = xv.w - ha.w;
        hv.x = omx * fmaf(a.x, ux * ux, hv.x);
        hv.y = omy * fmaf(a.y, uy * uy, hv.y);
        hv.z = omz * fmaf(a.z, uz * uz, hv.z);
        hv.w = omw * fmaf(a.w, uw * uw, hv.w);
        ha.x = fmaf(a.x, ux, ha.x);
        ha.y = fmaf(a.y, uy, ha.y);
        ha.z = fmaf(a.z, uz, ha.z);
        ha.w = fmaf(a.w, uw, ha.w);
        out4[((size_t)t * TWO_N + N_DIM + n) * DQ + g] =
            make_float4(sqrt_approx(hv.x), sqrt_approx(hv.y),
                        sqrt_approx(hv.z), sqrt_approx(hv.w));
    }

    if (s == SEG - 1) {
        // Final states: ha_N [N,D] then sqrt(hv_N) [N,D], appended after out
        const size_t base = (size_t)T_LEN * TWO_N * DQ;   // in float4 units
        out4[base + cg] = ha;
        out4[base + CG + cg] =
            make_float4(sqrt_approx(hv.x), sqrt_approx(hv.y),
                        sqrt_approx(hv.z), sqrt_approx(hv.w));
    }
}

// ---------------------------------------------------------------------------
extern "C" void kernel_launch(void* const* d_in, const int* in_sizes, int n_in,
                              void* d_out, int out_size) {
    const float4* x4  = (const float4*)d_in[0];   // [T, D]
    const float4* ha0 = (const float4*)d_in[1];   // [N, D]
    const float4* hs0 = (const float4*)d_in[2];   // [N, D]
    const float4* a4  = (const float4*)d_in[3];   // [N, D]
    float4* out4 = (float4*)d_out;

    k_b <<<BIG_THREADS / 256, 256>>>(x4, a4);
    k_ha<<<CG / 256, 256>>>(ha0, a4);
    k_a <<<BIG_THREADS / 256, 256>>>(x4, a4, out4);
    k_hv<<<CG / 256, 256>>>(hs0, a4);
    k_s <<<BIG_THREADS / 256, 256>>>(x4, a4, out4);
}